// round 2
// baseline (speedup 1.0000x reference)
#include <cuda_runtime.h>

// ROI-align-style pooling (RoiPoolingConv): img (1,128,128,1024) NHWC fp32,
// rois (1,256,4) [x,y,w,h] in pixels, out (1,256,7,7,1024) fp32.
//
// One block per (roi, iy, ix) bin; 256 threads x float4 = 1024 channels.
// L2-BANDWIDTH BOUND (~12 TB/s LTS cap). This version elides corner loads
// whose interpolation weight is exactly zero (tx==0 / ty==0) or whose data
// is bitwise-identical due to index clamping (gx1==gx0 / gy1==gy0).
// All skip conditions are uniform per block -> no divergence.

#define POOL  7
#define NROIS 256
#define HH    128
#define WW    128
#define CC    1024

__global__ __launch_bounds__(256, 8)
void roi_pool_kernel(const float* __restrict__ img,
                     const float* __restrict__ rois,
                     float* __restrict__ out)
{
    const int bin = blockIdx.x;           // 0 .. 256*49-1
    const int roi = bin / (POOL * POOL);
    const int b49 = bin - roi * (POOL * POOL);
    const int iy  = b49 / POOL;
    const int ix  = b49 - iy * POOL;

    // roi = [x, y, w, h]; c = (int)(roi * 1/16)  (truncation, same as astype)
    const float4 r = reinterpret_cast<const float4*>(rois)[roi];
    const int x0 = (int)(r.x * 0.0625f);
    const int y0 = (int)(r.y * 0.0625f);
    const int w  = (int)(r.z * 0.0625f);
    const int h  = (int)(r.w * 0.0625f);

    // sample coords: s = i * (dim / POOL)   (identical fp32 math to reference)
    const float sy = (float)iy * ((float)h / (float)POOL);
    const float sx = (float)ix * ((float)w / (float)POOL);
    const float fy = floorf(sy);
    const float fx = floorf(sx);
    const float ty = sy - fy;
    const float tx = sx - fx;

    const int y_lo = (int)fy;
    const int x_lo = (int)fx;
    const int y_hi = min(y_lo + 1, max(h - 1, 0));
    const int x_hi = min(x_lo + 1, max(w - 1, 0));

    const int gy0 = min(max(y0 + y_lo, 0), HH - 1);
    const int gy1 = min(max(y0 + y_hi, 0), HH - 1);
    const int gx0 = min(max(x0 + x_lo, 0), WW - 1);
    const int gx1 = min(max(x0 + x_hi, 0), WW - 1);

    // Load-elision flags (uniform across the block):
    //  - tx==0  -> v01/v11 multiplied by exactly 0, value irrelevant
    //  - gx1==gx0 -> v01 bitwise == v00, v11 bitwise == v10 (register copy)
    const bool need_x = (tx != 0.0f) && (gx1 != gx0);
    const bool need_y = (ty != 0.0f) && (gy1 != gy0);

    const float4* __restrict__ p00 =
        reinterpret_cast<const float4*>(img + (size_t)(gy0 * WW + gx0) * CC);
    const float4* __restrict__ p01 =
        reinterpret_cast<const float4*>(img + (size_t)(gy0 * WW + gx1) * CC);
    const float4* __restrict__ p10 =
        reinterpret_cast<const float4*>(img + (size_t)(gy1 * WW + gx0) * CC);
    const float4* __restrict__ p11 =
        reinterpret_cast<const float4*>(img + (size_t)(gy1 * WW + gx1) * CC);

    float4* __restrict__ po = reinterpret_cast<float4*>(out + (size_t)bin * CC);

    const int t = threadIdx.x;            // 0..255, 256 float4 = 1024 floats

    // Fallback assignments keep every skip case bit-exact:
    //  need_x=0: v01==v00 (clamp) or tx==0      -> b = a
    //  need_y=0: v10==v00 (clamp) or ty==0      -> c = a
    //  d: both needed -> load; need_y only -> v11==v10 -> d=c;
    //     else (need_y=0) bot is dead or equals top -> d=b works in all cases.
    const float4 a = p00[t];
    float4 b, c, d;
    if (need_x) b = p01[t]; else b = a;
    if (need_y) c = p10[t]; else c = a;
    if (need_x && need_y)      d = p11[t];
    else if (need_y)           d = c;
    else                       d = b;

    float4 o;
    {
        float top, bot;
        top = a.x + tx * (b.x - a.x);
        bot = c.x + tx * (d.x - c.x);
        o.x = top + ty * (bot - top);
        top = a.y + tx * (b.y - a.y);
        bot = c.y + tx * (d.y - c.y);
        o.y = top + ty * (bot - top);
        top = a.z + tx * (b.z - a.z);
        bot = c.z + tx * (d.z - c.z);
        o.z = top + ty * (bot - top);
        top = a.w + tx * (b.w - a.w);
        bot = c.w + tx * (d.w - c.w);
        o.w = top + ty * (bot - top);
    }
    po[t] = o;
}

extern "C" void kernel_launch(void* const* d_in, const int* in_sizes, int n_in,
                              void* d_out, int out_size)
{
    const float* img  = (const float*)d_in[0];
    const float* rois = (const float*)d_in[1];
    if (n_in >= 2 && in_sizes[0] < in_sizes[1]) {
        img  = (const float*)d_in[1];
        rois = (const float*)d_in[0];
    }
    float* out = (float*)d_out;

    const int nblocks = NROIS * POOL * POOL;   // 12544
    roi_pool_kernel<<<nblocks, 256>>>(img, rois, out);
}

// round 3
// speedup vs baseline: 1.4787x; 1.4787x over previous
#include <cuda_runtime.h>

// ROI-align-style pooling (RoiPoolingConv): img (1,128,128,1024) NHWC fp32,
// rois (1,256,4) [x,y,w,h] in pixels, out (1,256,7,7,1024) fp32.
//
// One block per (roi, iy, ix) bin; 256 threads x float4 = 1024 channels.
// L2-data-bandwidth bound (~12 TB/s LTS cap). Traffic reduction via ADDRESS
// SELECTION, not branches: when a corner's weight is exactly zero (tx==0 /
// ty==0) or its index is clamped equal (gx1==gx0 / gy1==gy0), its load
// address is redirected to an already-loaded corner. The 4 LDG.128s stay
// unconditional and front-batched (full MLP); duplicate addresses merge in
// the L1tex pending-miss queue and cost no L2 bandwidth.

#define POOL  7
#define NROIS 256
#define HH    128
#define WW    128
#define CC    1024

__global__ __launch_bounds__(256, 8)
void roi_pool_kernel(const float* __restrict__ img,
                     const float* __restrict__ rois,
                     float* __restrict__ out)
{
    const int bin = blockIdx.x;           // 0 .. 256*49-1
    const int roi = bin / (POOL * POOL);
    const int b49 = bin - roi * (POOL * POOL);
    const int iy  = b49 / POOL;
    const int ix  = b49 - iy * POOL;

    // roi = [x, y, w, h]; c = (int)(roi * 1/16)  (truncation, same as astype)
    const float4 r = reinterpret_cast<const float4*>(rois)[roi];
    const int x0 = (int)(r.x * 0.0625f);
    const int y0 = (int)(r.y * 0.0625f);
    const int w  = (int)(r.z * 0.0625f);
    const int h  = (int)(r.w * 0.0625f);

    // sample coords: s = i * (dim / POOL)   (identical fp32 math to reference)
    const float sy = (float)iy * ((float)h / (float)POOL);
    const float sx = (float)ix * ((float)w / (float)POOL);
    const float fy = floorf(sy);
    const float fx = floorf(sx);
    const float ty = sy - fy;
    const float tx = sx - fx;

    const int y_lo = (int)fy;
    const int x_lo = (int)fx;
    const int y_hi = min(y_lo + 1, max(h - 1, 0));
    const int x_hi = min(x_lo + 1, max(w - 1, 0));

    const int gy0 = min(max(y0 + y_lo, 0), HH - 1);
    const int gy1 = min(max(y0 + y_hi, 0), HH - 1);
    const int gx0 = min(max(x0 + x_lo, 0), WW - 1);
    const int gx1 = min(max(x0 + x_hi, 0), WW - 1);

    // When the hi corner is dead weight (t==0) or clamped identical, fold its
    // index onto the lo corner — pure integer SEL, no branch. Result is
    // bit-exact: either the loaded value is multiplied by exactly 0, or it is
    // bitwise equal to the lo corner's value anyway.
    const int ex = (tx != 0.0f && gx1 != gx0) ? gx1 : gx0;   // effective x_hi
    const int ey = (ty != 0.0f && gy1 != gy0) ? gy1 : gy0;   // effective y_hi

    const int t = threadIdx.x;            // 0..255, 256 float4 = 1024 floats

    const float4* __restrict__ imgv = reinterpret_cast<const float4*>(img);
    const size_t i00 = (size_t)(gy0 * WW + gx0) * (CC / 4) + t;
    const size_t i01 = (size_t)(gy0 * WW + ex ) * (CC / 4) + t;
    const size_t i10 = (size_t)(ey  * WW + gx0) * (CC / 4) + t;
    const size_t i11 = (size_t)(ey  * WW + ex ) * (CC / 4) + t;

    // 4 unconditional loads — front-batched, full MLP.
    const float4 a = imgv[i00];
    const float4 b = imgv[i01];
    const float4 c = imgv[i10];
    const float4 d = imgv[i11];

    float4 o;
    {
        float top, bot;
        top = a.x + tx * (b.x - a.x);
        bot = c.x + tx * (d.x - c.x);
        o.x = top + ty * (bot - top);
        top = a.y + tx * (b.y - a.y);
        bot = c.y + tx * (d.y - c.y);
        o.y = top + ty * (bot - top);
        top = a.z + tx * (b.z - a.z);
        bot = c.z + tx * (d.z - c.z);
        o.z = top + ty * (bot - top);
        top = a.w + tx * (b.w - a.w);
        bot = c.w + tx * (d.w - c.w);
        o.w = top + ty * (bot - top);
    }
    reinterpret_cast<float4*>(out + (size_t)bin * CC)[t] = o;
}

extern "C" void kernel_launch(void* const* d_in, const int* in_sizes, int n_in,
                              void* d_out, int out_size)
{
    const float* img  = (const float*)d_in[0];
    const float* rois = (const float*)d_in[1];
    if (n_in >= 2 && in_sizes[0] < in_sizes[1]) {
        img  = (const float*)d_in[1];
        rois = (const float*)d_in[0];
    }
    float* out = (float*)d_out;

    const int nblocks = NROIS * POOL * POOL;   // 12544
    roi_pool_kernel<<<nblocks, 256>>>(img, rois, out);
}

// round 4
// speedup vs baseline: 1.6387x; 1.1082x over previous
#include <cuda_runtime.h>

// ROI-align-style pooling (RoiPoolingConv): img (1,128,128,1024) NHWC fp32,
// rois (1,256,4) [x,y,w,h] px, out (1,256,7,7,1024) fp32.
//
// Two-kernel pipeline (one graph):
//  1) setup_kernel: one thread per bin (12544) computes corner offsets
//     (with zero-weight / clamp dedup folded into the offset, as in R3)
//     and interpolation weights -> __device__ scratch.
//  2) roi_pool_kernel: one block per bin, 256 threads x float4. Per thread:
//     2 uniform param loads + 4 front-batched LDG.128 + 24 FFMA + 1 STG.128.
//     ~45% fewer issue slots than computing setup per-thread.

#define POOL  7
#define NROIS 256
#define HH    128
#define WW    128
#define CC    1024
#define NBINS (NROIS * POOL * POOL)   // 12544

// Per-bin params: 4 corner offsets (in float4 units) + (tx, ty).
__device__ int4   g_offs[NBINS];
__device__ float2 g_ts[NBINS];

__global__ void setup_kernel(const float* __restrict__ rois)
{
    const int bin = blockIdx.x * blockDim.x + threadIdx.x;
    if (bin >= NBINS) return;

    const int roi = bin / (POOL * POOL);
    const int b49 = bin - roi * (POOL * POOL);
    const int iy  = b49 / POOL;
    const int ix  = b49 - iy * POOL;

    // roi = [x, y, w, h]; c = (int)(roi * 1/16)  (truncation, same as astype)
    const float4 r = reinterpret_cast<const float4*>(rois)[roi];
    const int x0 = (int)(r.x * 0.0625f);
    const int y0 = (int)(r.y * 0.0625f);
    const int w  = (int)(r.z * 0.0625f);
    const int h  = (int)(r.w * 0.0625f);

    // sample coords: s = i * (dim / POOL)   (identical fp32 math to reference)
    const float sy = (float)iy * ((float)h / (float)POOL);
    const float sx = (float)ix * ((float)w / (float)POOL);
    const float fy = floorf(sy);
    const float fx = floorf(sx);
    const float ty = sy - fy;
    const float tx = sx - fx;

    const int y_lo = (int)fy;
    const int x_lo = (int)fx;
    const int y_hi = min(y_lo + 1, max(h - 1, 0));
    const int x_hi = min(x_lo + 1, max(w - 1, 0));

    const int gy0 = min(max(y0 + y_lo, 0), HH - 1);
    const int gy1 = min(max(y0 + y_hi, 0), HH - 1);
    const int gx0 = min(max(x0 + x_lo, 0), WW - 1);
    const int gx1 = min(max(x0 + x_hi, 0), WW - 1);

    // Fold dead-weight (t==0) or clamp-identical hi corners onto the lo
    // corner: duplicate addresses merge in L1tex -> no extra L2 traffic.
    // Bit-exact: skipped value is multiplied by exactly 0 or is bitwise
    // identical to the lo corner.
    const int ex = (tx != 0.0f && gx1 != gx0) ? gx1 : gx0;
    const int ey = (ty != 0.0f && gy1 != gy0) ? gy1 : gy0;

    const int c4 = CC / 4;   // 256 float4 per pixel
    int4 o;
    o.x = (gy0 * WW + gx0) * c4;
    o.y = (gy0 * WW + ex ) * c4;
    o.z = (ey  * WW + gx0) * c4;
    o.w = (ey  * WW + ex ) * c4;
    g_offs[bin] = o;
    g_ts[bin]   = make_float2(tx, ty);
}

__global__ __launch_bounds__(256, 8)
void roi_pool_kernel(const float* __restrict__ img,
                     float* __restrict__ out)
{
    const int bin = blockIdx.x;
    const int t   = threadIdx.x;          // 0..255, 256 float4 = 1024 floats

    // Uniform across the block: broadcast loads, heavy L1 hits.
    const int4   o  = g_offs[bin];
    const float2 tw = g_ts[bin];
    const float  tx = tw.x;
    const float  ty = tw.y;

    const float4* __restrict__ imgv = reinterpret_cast<const float4*>(img);

    // 4 unconditional, front-batched LDG.128 — full MLP.
    const float4 a = imgv[o.x + t];
    const float4 b = imgv[o.y + t];
    const float4 c = imgv[o.z + t];
    const float4 d = imgv[o.w + t];

    float4 r;
    {
        float top, bot;
        top = a.x + tx * (b.x - a.x);
        bot = c.x + tx * (d.x - c.x);
        r.x = top + ty * (bot - top);
        top = a.y + tx * (b.y - a.y);
        bot = c.y + tx * (d.y - c.y);
        r.y = top + ty * (bot - top);
        top = a.z + tx * (b.z - a.z);
        bot = c.z + tx * (d.z - c.z);
        r.z = top + ty * (bot - top);
        top = a.w + tx * (b.w - a.w);
        bot = c.w + tx * (d.w - c.w);
        r.w = top + ty * (bot - top);
    }
    reinterpret_cast<float4*>(out)[(size_t)bin * (CC / 4) + t] = r;
}

extern "C" void kernel_launch(void* const* d_in, const int* in_sizes, int n_in,
                              void* d_out, int out_size)
{
    const float* img  = (const float*)d_in[0];
    const float* rois = (const float*)d_in[1];
    if (n_in >= 2 && in_sizes[0] < in_sizes[1]) {
        img  = (const float*)d_in[1];
        rois = (const float*)d_in[0];
    }
    float* out = (float*)d_out;

    setup_kernel<<<(NBINS + 255) / 256, 256>>>(rois);
    roi_pool_kernel<<<NBINS, 256>>>(img, out);
}